// round 7
// baseline (speedup 1.0000x reference)
#include <cuda_runtime.h>

// ---------------------------------------------------------------------------
// LSTM_6786048328562 : T=512, B=32, I=H=1024  (fp32 in/out, tf32 tensor math)
//   out = [ output(512*32*1024) | h_n(32*1024) | c_n(32*1024) ]
//
// Row reorder:  j'' = 32*blk + gate*8 + u   (hidden n = 8*blk + u, blk=0..127)
//
// prep    : reorder+tf32-round W,U; tf32-round x; bias; zero h; bars=0
// gemm_xg : xg = xr @ W''^T + bias  (tf32 mma.sync, 128x128x32, cp.async)
// lstm    : persistent 128 CTAs; TWO interleaved half-batch recurrences
//           (A = batch 0..15, B = 16..31), each with its own barrier, so
//           barrier/visibility/load latency of one half hides under the
//           other half's epilogue+MMA. U fragments in registers.
// ---------------------------------------------------------------------------

#define T_STEPS 512
#define BATCH   32
#define HID     1024
#define GATES   4096

__device__ float d_xg[67108864];           // [16384][4096]
__device__ float d_xr[16777216];           // tf32-rounded x
__device__ float d_Wp[GATES * HID];
__device__ float d_Up[GATES * HID];
__device__ float d_biasp[GATES];
__device__ float d_hbuf[2 * 2 * 16 * HID]; // [half][phase][16][1024]
__device__ unsigned g_bars[64];            // [0]=A, [32]=B (separate lines)

__device__ __forceinline__ float f2tf32(float f) {
    unsigned u;
    asm("cvt.rna.tf32.f32 %0, %1;" : "=r"(u) : "f"(f));
    return __uint_as_float(u);
}

__device__ __forceinline__ void mma_tf32(float* c, const unsigned* a, const unsigned* b) {
    asm volatile(
        "mma.sync.aligned.m16n8k8.row.col.f32.tf32.tf32.f32 "
        "{%0,%1,%2,%3}, {%4,%5,%6,%7}, {%8,%9}, {%0,%1,%2,%3};\n"
        : "+f"(c[0]), "+f"(c[1]), "+f"(c[2]), "+f"(c[3])
        : "r"(a[0]), "r"(a[1]), "r"(a[2]), "r"(a[3]), "r"(b[0]), "r"(b[1]));
}

__device__ __forceinline__ float sigm(float x) { return 1.0f / (1.0f + expf(-x)); }

#define CP_ASYNC_CG(dst, src) \
    asm volatile("cp.async.cg.shared.global [%0], [%1], 16;\n" :: "r"(dst), "l"(src))
#define CP_COMMIT() asm volatile("cp.async.commit_group;\n")
#define CP_WAIT(n)  asm volatile("cp.async.wait_group %0;\n" :: "n"(n))

// ---------------------------------------------------------------------------
__global__ void prep_kernel(const float* __restrict__ x,
                            const float* __restrict__ W, const float* __restrict__ U,
                            const float* __restrict__ bih, const float* __restrict__ bhh) {
    int tid = blockIdx.x * blockDim.x + threadIdx.x;
    int stride = gridDim.x * blockDim.x;
    if (tid < 64) g_bars[tid] = 0u;

    for (int idx = tid; idx < GATES * HID; idx += stride) {
        int jp = idx >> 10, k = idx & 1023;
        int blk = jp >> 5, r = jp & 31;
        int gate = r >> 3, u = r & 7;
        int j = gate * HID + (blk * 8 + u);
        d_Wp[idx] = f2tf32(W[j * HID + k]);
        d_Up[idx] = f2tf32(U[j * HID + k]);
    }
    for (int idx = tid; idx < 16777216; idx += stride) d_xr[idx] = f2tf32(x[idx]);
    for (int idx = tid; idx < GATES; idx += stride) {
        int blk = idx >> 5, r = idx & 31;
        int gate = r >> 3, u = r & 7;
        int j = gate * HID + (blk * 8 + u);
        d_biasp[idx] = bih[j] + bhh[j];
    }
    for (int idx = tid; idx < 2 * 2 * 16 * HID; idx += stride) d_hbuf[idx] = 0.0f;
}

// ---------------------------------------------------------------------------
// Phase 1: xg = xr @ Wp^T + bias   (M=16384, N=4096, K=1024)  — unchanged R4
// ---------------------------------------------------------------------------
#define P1_S 36

__global__ __launch_bounds__(256, 2) void gemm_xg() {
    extern __shared__ float sm1[];
    float* As = sm1;
    float* Bs = sm1 + 2 * 128 * P1_S;

    const int n0 = blockIdx.x * 128;
    const int m0 = blockIdx.y * 128;
    const int tid = threadIdx.x;
    const int warp = tid >> 5, lane = tid & 31;
    const int wm = warp >> 2, wn = warp & 3;
    const int gid = lane >> 2, tg = lane & 3;

    float acc[4][4][4];
#pragma unroll
    for (int i = 0; i < 4; i++)
#pragma unroll
        for (int j = 0; j < 4; j++)
#pragma unroll
            for (int k = 0; k < 4; k++) acc[i][j][k] = 0.0f;

    const float* Ag = d_xr + (size_t)m0 * HID;
    const float* Bg = d_Wp + (size_t)n0 * HID;

    auto load_stage = [&](int kt, int st) {
        float* Ad = As + st * 128 * P1_S;
        float* Bd = Bs + st * 128 * P1_S;
        const int k0 = kt * 32;
#pragma unroll
        for (int l = 0; l < 4; l++) {
            int i = tid + l * 256;
            int row = i >> 3, v = (i & 7) * 4;
            unsigned da = (unsigned)__cvta_generic_to_shared(Ad + row * P1_S + v);
            CP_ASYNC_CG(da, Ag + (size_t)row * HID + k0 + v);
            unsigned db = (unsigned)__cvta_generic_to_shared(Bd + row * P1_S + v);
            CP_ASYNC_CG(db, Bg + (size_t)row * HID + k0 + v);
        }
        CP_COMMIT();
    };

    load_stage(0, 0);
    for (int kt = 0; kt < 32; kt++) {
        if (kt + 1 < 32) { load_stage(kt + 1, (kt + 1) & 1); CP_WAIT(1); }
        else             { CP_WAIT(0); }
        __syncthreads();
        const float* Ac = As + (kt & 1) * 128 * P1_S;
        const float* Bc = Bs + (kt & 1) * 128 * P1_S;
#pragma unroll
        for (int kk = 0; kk < 4; kk++) {
            const int kc = kk * 8 + tg;
            unsigned a[4][4], b[4][2];
#pragma unroll
            for (int mf = 0; mf < 4; mf++) {
                int row = wm * 64 + mf * 16 + gid;
                a[mf][0] = __float_as_uint(Ac[row * P1_S + kc]);
                a[mf][1] = __float_as_uint(Ac[(row + 8) * P1_S + kc]);
                a[mf][2] = __float_as_uint(Ac[row * P1_S + kc + 4]);
                a[mf][3] = __float_as_uint(Ac[(row + 8) * P1_S + kc + 4]);
            }
#pragma unroll
            for (int nf = 0; nf < 4; nf++) {
                int col = wn * 32 + nf * 8 + gid;
                b[nf][0] = __float_as_uint(Bc[col * P1_S + kc]);
                b[nf][1] = __float_as_uint(Bc[col * P1_S + kc + 4]);
            }
#pragma unroll
            for (int mf = 0; mf < 4; mf++)
#pragma unroll
                for (int nf = 0; nf < 4; nf++) mma_tf32(acc[mf][nf], a[mf], b[nf]);
        }
        __syncthreads();
    }

#pragma unroll
    for (int mf = 0; mf < 4; mf++)
#pragma unroll
        for (int nf = 0; nf < 4; nf++) {
            int row = m0 + wm * 64 + mf * 16 + gid;
            int col = n0 + wn * 32 + nf * 8 + 2 * tg;
            float b0 = d_biasp[col], b1 = d_biasp[col + 1];
            d_xg[(size_t)row * GATES + col]           = acc[mf][nf][0] + b0;
            d_xg[(size_t)row * GATES + col + 1]       = acc[mf][nf][1] + b1;
            d_xg[(size_t)(row + 8) * GATES + col]     = acc[mf][nf][2] + b0;
            d_xg[(size_t)(row + 8) * GATES + col + 1] = acc[mf][nf][3] + b1;
        }
}

// ---------------------------------------------------------------------------
// Phase 2: interleaved half-batch persistent recurrence.
// smem (floats): hs 4 x (16 x 516)  | rb 4 x (32 x 17) | hstg 16 x 9
//   hs buffers: (half, chunk): A0, A1, B0, B1. chunk = 512 k.
// ---------------------------------------------------------------------------
#define SHW 516
#define HS_CH (16 * SHW)                  // 8256
#define RB2 (32 * 17)                     // 544
#define OFF_RB (4 * HS_CH)                // 33024
#define OFF_HSTG (OFF_RB + 4 * RB2)       // 35200
#define SM2_FLOATS (OFF_HSTG + 16 * 9 + 16)

__global__ __launch_bounds__(256, 1) void lstm_kernel(float* __restrict__ out) {
    extern __shared__ float sm[];
    float* hs   = sm;
    float* rb   = sm + OFF_RB;
    float* hstg = sm + OFF_HSTG;

    const int cta = blockIdx.x;
    const int tid = threadIdx.x;
    const int warp = tid >> 5, lane = tid & 31;
    const int gid = lane >> 2, tg = lane & 3;

    const unsigned long long barA =
        (unsigned long long)__cvta_generic_to_global(&g_bars[0]);
    const unsigned long long barB =
        (unsigned long long)__cvta_generic_to_global(&g_bars[32]);

    // ---- stage U'' fragments into registers (one-time), via hs scratch ----
    // aF[ch][kk][mt][4]: chunk ch (k in [512ch,512ch+512)), warp covers
    // k-range [512ch + 64*warp, +64) => kk=0..7 sub-steps of k8.
    unsigned aF[2][8][2][4];
    {
        const float* Ug = d_Up + (size_t)(32 * cta) * HID;
        for (int ch = 0; ch < 2; ch++) {
            for (int i = tid; i < 32 * 128; i += 256) {
                int row = i >> 7, v = (i & 127) * 4;
                *(float4*)(hs + row * SHW + v) =
                    *(const float4*)(Ug + row * HID + ch * 512 + v);
            }
            __syncthreads();
#pragma unroll
            for (int kk = 0; kk < 8; kk++) {
                const int kc = warp * 64 + kk * 8 + tg;
#pragma unroll
                for (int mt = 0; mt < 2; mt++) {
                    int row = mt * 16 + gid;
                    aF[ch][kk][mt][0] = __float_as_uint(hs[row * SHW + kc]);
                    aF[ch][kk][mt][1] = __float_as_uint(hs[(row + 8) * SHW + kc]);
                    aF[ch][kk][mt][2] = __float_as_uint(hs[row * SHW + kc + 4]);
                    aF[ch][kk][mt][3] = __float_as_uint(hs[(row + 8) * SHW + kc + 4]);
                }
            }
            __syncthreads();
        }
    }

    const bool active = (tid & 16) == 0;   // gate-math owner: u=warp, b=tid&15
    const int gu = warp, gb = tid & 15;
    // coalesced-store mapping (warps 0..3): b = 4w + lane>>3, u = lane&7
    const int sb = 4 * warp + (lane >> 3);
    const int su = lane & 7;
    const int sn = 8 * cta + su;

    float accA[2][2][4], accB[2][2][4];
#pragma unroll
    for (int i = 0; i < 2; i++)
#pragma unroll
        for (int j = 0; j < 2; j++)
#pragma unroll
            for (int k = 0; k < 4; k++) { accA[i][j][k] = 0.0f; accB[i][j][k] = 0.0f; }
    float cA = 0.0f, cB = 0.0f;
    float xgA[4], xgB[4];

    auto spin = [&](unsigned long long bp, unsigned target) {
        if (tid == 0) {
            unsigned v;
            do {
                asm volatile("ld.acquire.gpu.global.u32 %0, [%1];"
                             : "=r"(v) : "l"(bp) : "memory");
            } while (v < target);
        }
        __syncthreads();
    };

    auto load_chunk = [&](int H, int ch, int t) {
        const float* src = d_hbuf + H * (2 * 16 * HID) + (t & 1) * (16 * HID) + ch * 512;
        float* dst = hs + (H * 2 + ch) * HS_CH;
#pragma unroll
        for (int l = 0; l < 8; l++) {
            int i = tid + l * 256;
            int row = i >> 7, seg = (i & 127) * 4;
            unsigned d = (unsigned)__cvta_generic_to_shared(dst + row * SHW + seg);
            CP_ASYNC_CG(d, src + row * HID + seg);
        }
        CP_COMMIT();
    };

    auto load_xg = [&](float* dst, int H, int t) {
        if (active) {
            const float* p = d_xg + (size_t)(t * BATCH + H * 16 + gb) * GATES + 32 * cta;
#pragma unroll
            for (int g4 = 0; g4 < 4; g4++) dst[g4] = __ldg(p + g4 * 8 + gu);
        }
    };

#define MMA_CH(acc, H, CH) do {                                               \
    const float* hc = hs + ((H) * 2 + (CH)) * HS_CH;                          \
    _Pragma("unroll")                                                         \
    for (int kk = 0; kk < 8; kk++) {                                          \
        const int kcl = warp * 64 + kk * 8 + tg;                              \
        _Pragma("unroll")                                                     \
        for (int nf = 0; nf < 2; nf++) {                                      \
            unsigned b[2];                                                    \
            b[0] = __float_as_uint(hc[(nf * 8 + gid) * SHW + kcl]);           \
            b[1] = __float_as_uint(hc[(nf * 8 + gid) * SHW + kcl + 4]);       \
            _Pragma("unroll")                                                 \
            for (int mt = 0; mt < 2; mt++)                                    \
                mma_tf32((acc)[mt][nf], aF[CH][kk][mt], b);                   \
        }                                                                     \
    }                                                                         \
} while (0)

    auto epilogue = [&](float (*acc)[2][4], const float* xg4, float& c_reg,
                        int H, int t, bool last, unsigned long long bp) {
        float* rbw = rb + (warp & 3) * RB2;
        if (warp < 4) {
#pragma unroll
            for (int mt = 0; mt < 2; mt++)
#pragma unroll
                for (int nf = 0; nf < 2; nf++) {
                    int row = mt * 16 + gid;
                    int col = nf * 8 + 2 * tg;
                    rbw[row * 17 + col]           = acc[mt][nf][0];
                    rbw[row * 17 + col + 1]       = acc[mt][nf][1];
                    rbw[(row + 8) * 17 + col]     = acc[mt][nf][2];
                    rbw[(row + 8) * 17 + col + 1] = acc[mt][nf][3];
                }
        }
        __syncthreads();
        if (warp >= 4) {
#pragma unroll
            for (int mt = 0; mt < 2; mt++)
#pragma unroll
                for (int nf = 0; nf < 2; nf++) {
                    int row = mt * 16 + gid;
                    int col = nf * 8 + 2 * tg;
                    rbw[row * 17 + col]           += acc[mt][nf][0];
                    rbw[row * 17 + col + 1]       += acc[mt][nf][1];
                    rbw[(row + 8) * 17 + col]     += acc[mt][nf][2];
                    rbw[(row + 8) * 17 + col + 1] += acc[mt][nf][3];
                }
        }
        __syncthreads();
        if (active) {
            float v[4];
#pragma unroll
            for (int gate = 0; gate < 4; gate++) {
                int r = gate * 8 + gu;
                float s = xg4[gate];
#pragma unroll
                for (int p = 0; p < 4; p++) s += rb[p * RB2 + r * 17 + gb];
                v[gate] = s;
            }
            float it = sigm(v[0]);
            float ft = sigm(v[1]);
            float ch = tanhf(v[2]);
            float ot = sigm(v[3]);
            c_reg = ft * c_reg + it * ch;
            float h = ot * tanhf(c_reg);
            hstg[gb * 9 + gu] = h;
        }
        __syncthreads();
        float hval = 0.0f;
        if (warp < 4) {
            hval = hstg[sb * 9 + su];
            d_hbuf[H * (2 * 16 * HID) + ((t + 1) & 1) * (16 * HID) + sb * HID + sn]
                = f2tf32(hval);
        }
        __syncthreads();                     // order STGs before the release
        if (tid == 0)
            asm volatile("red.release.gpu.global.add.u32 [%0], %1;"
                         :: "l"(bp), "r"(1u) : "memory");
        if (warp < 4) {
            int bg = H * 16 + sb;
            out[(size_t)t * (BATCH * HID) + bg * HID + sn] = hval;
            if (last) out[16777216 + bg * HID + sn] = hval;   // h_n
        }
        if (last) {                          // c_n via transpose staging
            __syncthreads();
            if (active) hstg[gb * 9 + gu] = c_reg;
            __syncthreads();
            if (warp < 4)
                out[16777216 + 32768 + (H * 16 + sb) * HID + sn] = hstg[sb * 9 + su];
        }
#pragma unroll
        for (int i = 0; i < 2; i++)
#pragma unroll
            for (int j = 0; j < 2; j++)
#pragma unroll
                for (int k = 0; k < 4; k++) acc[i][j][k] = 0.0f;
    };

    for (int t = 0; t < T_STEPS; t++) {
        if (t) spin(barA, 128u * (unsigned)t);
        load_chunk(0, 0, t);
        load_chunk(0, 1, t);
        load_xg(xgA, 0, t);
        if (t) epilogue(accB, xgB, cB, 1, t - 1, false, barB);   // B(t-1)
        load_xg(xgB, 1, t);                                      // for next iter
        CP_WAIT(1); __syncthreads(); MMA_CH(accA, 0, 0);
        CP_WAIT(0); __syncthreads(); MMA_CH(accA, 0, 1);
        if (t) spin(barB, 128u * (unsigned)t);
        load_chunk(1, 0, t);
        load_chunk(1, 1, t);
        epilogue(accA, xgA, cA, 0, t, t == T_STEPS - 1, barA);   // A(t)
        CP_WAIT(1); __syncthreads(); MMA_CH(accB, 1, 0);
        CP_WAIT(0); __syncthreads(); MMA_CH(accB, 1, 1);
    }
    // drain: B(511)
    epilogue(accB, xgB, cB, 1, T_STEPS - 1, true, barB);
}

// ---------------------------------------------------------------------------
extern "C" void kernel_launch(void* const* d_in, const int* in_sizes, int n_in,
                              void* d_out, int out_size) {
    (void)in_sizes; (void)n_in; (void)out_size;
    const float* x   = (const float*)d_in[0];
    const float* W   = (const float*)d_in[1];
    const float* U   = (const float*)d_in[2];
    const float* bih = (const float*)d_in[3];
    const float* bhh = (const float*)d_in[4];
    float* out = (float*)d_out;

    static int inited = 0;
    const int smem1 = 2 * 2 * 128 * P1_S * 4;     // 73,728
    const int smem2 = SM2_FLOATS * 4;             // ~141,440
    if (!inited) {
        cudaFuncSetAttribute(gemm_xg, cudaFuncAttributeMaxDynamicSharedMemorySize, smem1);
        cudaFuncSetAttribute(lstm_kernel, cudaFuncAttributeMaxDynamicSharedMemorySize, smem2);
        inited = 1;
    }

    prep_kernel<<<4096, 256>>>(x, W, U, bih, bhh);
    dim3 g1(32, 128);
    gemm_xg<<<g1, 256, smem1>>>();
    lstm_kernel<<<128, 256, smem2>>>(out);
}

// round 9
// speedup vs baseline: 1.3557x; 1.3557x over previous
#include <cuda_runtime.h>
#include <cuda_fp16.h>

// ---------------------------------------------------------------------------
// LSTM_6786048328562 : T=512, B=32, I=H=1024  (fp32 in/out, fp16 tensor math
//   with fp32 accumulate — fp16 mantissa == tf32 mantissa, 2x throughput)
//   out = [ output(512*32*1024) | h_n(32*1024) | c_n(32*1024) ]
//
// Row reorder:  j'' = 32*blk + gate*8 + u   (hidden n = 8*blk + u, blk=0..127)
//
// prep    : reorder+fp16-round W,U; fp16 x; bias; zero h; bar=0
// gemm_xg : xg = xh @ Wh''^T + bias  (m16n8k16 f16 mma, 128x128x32, cp.async)
// lstm    : persistent 128 CTAs (R4 structure). U'' fragments in registers
//           (64 regs). Per step: issue xg(t+1) + 2 h half-chunks (K=512),
//           progressive wait/mma, two-phase smem reduce, gate math (c in
//           regs), coalesced fp16 h store, sync, release, out stores
//           overlap the barrier spin.
// ---------------------------------------------------------------------------

#define T_STEPS 512
#define BATCH   32
#define HID     1024
#define GATES   4096

__device__ float  d_xg[67108864];            // [16384][4096] fp32
__device__ __half d_xh[16777216];            // fp16 x
__device__ __half d_Wh[GATES * HID];
__device__ __half d_Uh[GATES * HID];
__device__ float  d_biasp[GATES];
__device__ __half d_hbuf[2 * BATCH * HID];   // double-buffered h (fp16)
__device__ unsigned g_bar;

__device__ __forceinline__ void mma_f16(float* c, const unsigned* a, const unsigned* b) {
    asm volatile(
        "mma.sync.aligned.m16n8k16.row.col.f32.f16.f16.f32 "
        "{%0,%1,%2,%3}, {%4,%5,%6,%7}, {%8,%9}, {%0,%1,%2,%3};\n"
        : "+f"(c[0]), "+f"(c[1]), "+f"(c[2]), "+f"(c[3])
        : "r"(a[0]), "r"(a[1]), "r"(a[2]), "r"(a[3]), "r"(b[0]), "r"(b[1]));
}

__device__ __forceinline__ float sigm(float x) { return 1.0f / (1.0f + expf(-x)); }

#define CP_ASYNC_CG(dst, src) \
    asm volatile("cp.async.cg.shared.global [%0], [%1], 16;\n" :: "r"(dst), "l"(src))
#define CP_COMMIT() asm volatile("cp.async.commit_group;\n")
#define CP_WAIT(n)  asm volatile("cp.async.wait_group %0;\n" :: "n"(n))

// ---------------------------------------------------------------------------
__global__ void prep_kernel(const float* __restrict__ x,
                            const float* __restrict__ W, const float* __restrict__ U,
                            const float* __restrict__ bih, const float* __restrict__ bhh) {
    int tid = blockIdx.x * blockDim.x + threadIdx.x;
    int stride = gridDim.x * blockDim.x;
    if (tid == 0) g_bar = 0u;

    for (int idx = tid; idx < GATES * HID; idx += stride) {
        int jp = idx >> 10, k = idx & 1023;
        int blk = jp >> 5, r = jp & 31;
        int gate = r >> 3, u = r & 7;
        int j = gate * HID + (blk * 8 + u);
        d_Wh[idx] = __float2half_rn(W[j * HID + k]);
        d_Uh[idx] = __float2half_rn(U[j * HID + k]);
    }
    for (int idx = tid; idx < 16777216; idx += stride)
        d_xh[idx] = __float2half_rn(x[idx]);
    for (int idx = tid; idx < GATES; idx += stride) {
        int blk = idx >> 5, r = idx & 31;
        int gate = r >> 3, u = r & 7;
        int j = gate * HID + (blk * 8 + u);
        d_biasp[idx] = bih[j] + bhh[j];
    }
    for (int idx = tid; idx < 2 * BATCH * HID; idx += stride)
        d_hbuf[idx] = __float2half_rn(0.0f);
}

// ---------------------------------------------------------------------------
// Phase 1: xg = xh @ Wh^T + bias   (M=16384, N=4096, K=1024), fp16 mma.
// 128x128 CTA tile, BK=32, 8 warps (2m x 4n), warp tile 64x32.
// ---------------------------------------------------------------------------
#define P1H 40   // half stride per 32-k row (bank-conflict-free fragments)

__global__ __launch_bounds__(256, 2) void gemm_xg() {
    extern __shared__ __half sm1[];
    __half* As = sm1;                   // [2][128*P1H]
    __half* Bs = sm1 + 2 * 128 * P1H;   // [2][128*P1H]

    const int n0 = blockIdx.x * 128;
    const int m0 = blockIdx.y * 128;
    const int tid = threadIdx.x;
    const int warp = tid >> 5, lane = tid & 31;
    const int wm = warp >> 2, wn = warp & 3;
    const int gid = lane >> 2, tg = lane & 3;

    float acc[4][4][4];
#pragma unroll
    for (int i = 0; i < 4; i++)
#pragma unroll
        for (int j = 0; j < 4; j++)
#pragma unroll
            for (int k = 0; k < 4; k++) acc[i][j][k] = 0.0f;

    const __half* Ag = d_xh + (size_t)m0 * HID;
    const __half* Bg = d_Wh + (size_t)n0 * HID;

    auto load_stage = [&](int kt, int st) {
        __half* Ad = As + st * 128 * P1H;
        __half* Bd = Bs + st * 128 * P1H;
        const int k0 = kt * 32;
#pragma unroll
        for (int l = 0; l < 2; l++) {
            int i = tid + l * 256;            // 0..511
            int row = i >> 2, seg = i & 3;    // 4 x 16B (8 halves) per row
            unsigned da = (unsigned)__cvta_generic_to_shared(Ad + row * P1H + seg * 8);
            CP_ASYNC_CG(da, Ag + (size_t)row * HID + k0 + seg * 8);
            unsigned db = (unsigned)__cvta_generic_to_shared(Bd + row * P1H + seg * 8);
            CP_ASYNC_CG(db, Bg + (size_t)row * HID + k0 + seg * 8);
        }
        CP_COMMIT();
    };

    load_stage(0, 0);
    for (int kt = 0; kt < 32; kt++) {
        if (kt + 1 < 32) { load_stage(kt + 1, (kt + 1) & 1); CP_WAIT(1); }
        else             { CP_WAIT(0); }
        __syncthreads();
        const __half* Ac = As + (kt & 1) * 128 * P1H;
        const __half* Bc = Bs + (kt & 1) * 128 * P1H;
#pragma unroll
        for (int ks = 0; ks < 2; ks++) {
            const int kb = ks * 16;
            unsigned a[4][4], b[4][2];
#pragma unroll
            for (int mf = 0; mf < 4; mf++) {
                int row = wm * 64 + mf * 16 + gid;
                a[mf][0] = *(const unsigned*)&Ac[row * P1H + kb + 2 * tg];
                a[mf][1] = *(const unsigned*)&Ac[(row + 8) * P1H + kb + 2 * tg];
                a[mf][2] = *(const unsigned*)&Ac[row * P1H + kb + 8 + 2 * tg];
                a[mf][3] = *(const unsigned*)&Ac[(row + 8) * P1H + kb + 8 + 2 * tg];
            }
#pragma unroll
            for (int nf = 0; nf < 4; nf++) {
                int col = wn * 32 + nf * 8 + gid;
                b[nf][0] = *(const unsigned*)&Bc[col * P1H + kb + 2 * tg];
                b[nf][1] = *(const unsigned*)&Bc[col * P1H + kb + 8 + 2 * tg];
            }
#pragma unroll
            for (int mf = 0; mf < 4; mf++)
#pragma unroll
                for (int nf = 0; nf < 4; nf++) mma_f16(acc[mf][nf], a[mf], b[nf]);
        }
        __syncthreads();
    }

#pragma unroll
    for (int mf = 0; mf < 4; mf++)
#pragma unroll
        for (int nf = 0; nf < 4; nf++) {
            int row = m0 + wm * 64 + mf * 16 + gid;
            int col = n0 + wn * 32 + nf * 8 + 2 * tg;
            float b0 = d_biasp[col], b1 = d_biasp[col + 1];
            d_xg[(size_t)row * GATES + col]           = acc[mf][nf][0] + b0;
            d_xg[(size_t)row * GATES + col + 1]       = acc[mf][nf][1] + b1;
            d_xg[(size_t)(row + 8) * GATES + col]     = acc[mf][nf][2] + b0;
            d_xg[(size_t)(row + 8) * GATES + col + 1] = acc[mf][nf][3] + b1;
        }
}

// ---------------------------------------------------------------------------
// Phase 2: persistent recurrence, fp16 MMA. 128 CTAs, 32 gate-rows, full K.
// smem: hs 2 x [32][520] half | rb 4 x [32][33] f32 | xs 2x[32][36] f32 |
//       hstg [32][9] f32
// ---------------------------------------------------------------------------
#define SH2 520                            // halves per h row (K=512 + pad)
#define HS_CH (32 * SH2)                   // halves per chunk buffer
#define HS_BYTES (2 * HS_CH * 2)           // 66,560
#define RB_OFF HS_BYTES
#define RBS (32 * 33)
#define XS_OFF (RB_OFF + 4 * RBS * 4)      // +16,896 = 83,456
#define HSTG_OFF (XS_OFF + 2 * 32 * 36 * 4) // +9,216 = 92,672
#define SM2_BYTES (HSTG_OFF + 32 * 9 * 4 + 64) // 93,888

__global__ __launch_bounds__(256, 1) void lstm_kernel(float* __restrict__ out) {
    extern __shared__ char smc[];
    __half* hs   = (__half*)smc;
    float*  rb   = (float*)(smc + RB_OFF);
    float*  xs   = (float*)(smc + XS_OFF);
    float*  hstg = (float*)(smc + HSTG_OFF);

    const int cta = blockIdx.x;
    const int tid = threadIdx.x;
    const int warp = tid >> 5, lane = tid & 31;
    const int gid = lane >> 2, tg = lane & 3;

    const unsigned long long barp =
        (unsigned long long)__cvta_generic_to_global(&g_bar);

    // ---- stage U'' fragments into registers (one-time, via hs scratch) ----
    // aF[ch][ks][mt][4]: chunk ch (k in [512ch,+512)), warp k-range
    // [512ch + 64*warp, +64), ks = k16 step 0..3, mt = row-half.
    unsigned aF[2][4][2][4];
    {
        const __half* Ug = d_Uh + (size_t)(32 * cta) * HID;
        for (int ch = 0; ch < 2; ch++) {
            for (int i = tid; i < 32 * 64; i += 256) {
                int row = i >> 6, seg = i & 63;   // 64 x 8 halves
                *(float4*)(hs + row * SH2 + seg * 8) =
                    *(const float4*)(Ug + row * HID + ch * 512 + seg * 8);
            }
            __syncthreads();
#pragma unroll
            for (int ks = 0; ks < 4; ks++) {
                const int kc = warp * 64 + ks * 16 + 2 * tg;
#pragma unroll
                for (int mt = 0; mt < 2; mt++) {
                    int row = mt * 16 + gid;
                    aF[ch][ks][mt][0] = *(const unsigned*)&hs[row * SH2 + kc];
                    aF[ch][ks][mt][1] = *(const unsigned*)&hs[(row + 8) * SH2 + kc];
                    aF[ch][ks][mt][2] = *(const unsigned*)&hs[row * SH2 + kc + 8];
                    aF[ch][ks][mt][3] = *(const unsigned*)&hs[(row + 8) * SH2 + kc + 8];
                }
            }
            __syncthreads();
        }
    }

    // prefetch xg for t=0 into xs[0]
    {
        int row = tid >> 3, q = tid & 7;
        unsigned d = (unsigned)__cvta_generic_to_shared(xs + row * 36 + q * 4);
        CP_ASYNC_CG(d, d_xg + (size_t)row * GATES + 32 * cta + q * 4);
        CP_COMMIT();
    }

    const int tu = tid >> 5, tb = tid & 31;   // gate-math owner (u=tu, b=tb)
    float c_reg = 0.0f;

    // coalesced-store mapping: warp w -> b = 4w + lane>>3, u = lane&7
    const int wb = 4 * warp + (lane >> 3);
    const int wu = lane & 7;
    const int wn_idx = 8 * cta + wu;

    for (int t = 0; t < T_STEPS; t++) {
        const __half* hb = d_hbuf + (t & 1) * (BATCH * HID);

        // issue xg(t+1) prefetch + both h chunks
        if (t + 1 < T_STEPS) {
            int row = tid >> 3, q = tid & 7;
            unsigned d = (unsigned)__cvta_generic_to_shared(
                xs + ((t + 1) & 1) * (32 * 36) + row * 36 + q * 4);
            CP_ASYNC_CG(d, d_xg + (size_t)((t + 1) * BATCH + row) * GATES
                            + 32 * cta + q * 4);
            CP_COMMIT();
        }
#pragma unroll
        for (int ch = 0; ch < 2; ch++) {
#pragma unroll
            for (int l = 0; l < 8; l++) {
                int i = tid + l * 256;            // 0..2047
                int row = i >> 6, seg = i & 63;   // 64 x 16B per row
                unsigned d = (unsigned)__cvta_generic_to_shared(
                    hs + ch * HS_CH + row * SH2 + seg * 8);
                CP_ASYNC_CG(d, hb + row * HID + ch * 512 + seg * 8);
            }
            CP_COMMIT();
        }

        float acc[2][4][4];
#pragma unroll
        for (int i = 0; i < 2; i++)
#pragma unroll
            for (int j = 0; j < 4; j++)
#pragma unroll
                for (int k = 0; k < 4; k++) acc[i][j][k] = 0.0f;

        auto mma_chunk = [&](int ch) {
            const __half* hc = hs + ch * HS_CH;
#pragma unroll
            for (int ks = 0; ks < 4; ks++) {
                const int kcl = warp * 64 + ks * 16 + 2 * tg;
#pragma unroll
                for (int nf = 0; nf < 4; nf++) {
                    unsigned b[2];
                    b[0] = *(const unsigned*)&hc[(nf * 8 + gid) * SH2 + kcl];
                    b[1] = *(const unsigned*)&hc[(nf * 8 + gid) * SH2 + kcl + 8];
#pragma unroll
                    for (int mt = 0; mt < 2; mt++)
                        mma_f16(acc[mt][nf], aF[ch][ks][mt], b);
                }
            }
        };

        CP_WAIT(1); __syncthreads(); mma_chunk(0);
        CP_WAIT(0); __syncthreads(); mma_chunk(1);

        // two-phase reduce: warps 0-3 dump, warps 4-7 accumulate
        {
            float* rbw = rb + (warp & 3) * RBS;
            if (warp < 4) {
#pragma unroll
                for (int mt = 0; mt < 2; mt++)
#pragma unroll
                    for (int nf = 0; nf < 4; nf++) {
                        int row = mt * 16 + gid;
                        int col = nf * 8 + 2 * tg;
                        rbw[row * 33 + col]           = acc[mt][nf][0];
                        rbw[row * 33 + col + 1]       = acc[mt][nf][1];
                        rbw[(row + 8) * 33 + col]     = acc[mt][nf][2];
                        rbw[(row + 8) * 33 + col + 1] = acc[mt][nf][3];
                    }
            }
            __syncthreads();
            if (warp >= 4) {
#pragma unroll
                for (int mt = 0; mt < 2; mt++)
#pragma unroll
                    for (int nf = 0; nf < 4; nf++) {
                        int row = mt * 16 + gid;
                        int col = nf * 8 + 2 * tg;
                        rbw[row * 33 + col]           += acc[mt][nf][0];
                        rbw[row * 33 + col + 1]       += acc[mt][nf][1];
                        rbw[(row + 8) * 33 + col]     += acc[mt][nf][2];
                        rbw[(row + 8) * 33 + col + 1] += acc[mt][nf][3];
                    }
            }
            __syncthreads();
        }

        // gate math (thread owns u=tu, b=tb); stage h via transpose buffer
        float c_save = 0.0f;
        {
            const float* xgr = xs + (t & 1) * (32 * 36) + tb * 36;
            float v[4];
#pragma unroll
            for (int gate = 0; gate < 4; gate++) {
                int r = gate * 8 + tu;
                float s = xgr[r];
#pragma unroll
                for (int p = 0; p < 4; p++) s += rb[p * RBS + r * 33 + tb];
                v[gate] = s;
            }
            float it = sigm(v[0]);
            float ft = sigm(v[1]);
            float ch = tanhf(v[2]);
            float ot = sigm(v[3]);
            c_reg = ft * c_reg + it * ch;
            c_save = c_reg;
            float h = ot * tanhf(c_reg);
            hstg[tb * 9 + tu] = h;
        }
        __syncthreads();

        // coalesced fp16 h write to d_hbuf
        float hval = hstg[wb * 9 + wu];
        if (t + 1 < T_STEPS)
            d_hbuf[((t + 1) & 1) * (BATCH * HID) + wb * HID + wn_idx]
                = __float2half_rn(hval);

        __syncthreads();                    // order h stores before release
        if (tid == 0)
            asm volatile("red.release.gpu.global.add.u32 [%0], %1;"
                         :: "l"(barp), "r"(1u) : "memory");

        // out stores overlap the barrier spin
        out[(size_t)t * (BATCH * HID) + wb * HID + wn_idx] = hval;
        if (t == T_STEPS - 1) {
            out[16777216 + wb * HID + wn_idx] = hval;         // h_n
            __syncthreads();
            hstg[tb * 9 + tu] = c_save;
            __syncthreads();
            out[16777216 + 32768 + wb * HID + wn_idx] = hstg[wb * 9 + wu];
        }

        if (tid == 0) {
            const unsigned target = 128u * (unsigned)(t + 1);
            unsigned v;
            do {
                asm volatile("ld.acquire.gpu.global.u32 %0, [%1];"
                             : "=r"(v) : "l"(barp) : "memory");
            } while (v < target);
        }
        __syncthreads();
    }
}

// ---------------------------------------------------------------------------
extern "C" void kernel_launch(void* const* d_in, const int* in_sizes, int n_in,
                              void* d_out, int out_size) {
    (void)in_sizes; (void)n_in; (void)out_size;
    const float* x   = (const float*)d_in[0];
    const float* W   = (const float*)d_in[1];
    const float* U   = (const float*)d_in[2];
    const float* bih = (const float*)d_in[3];
    const float* bhh = (const float*)d_in[4];
    float* out = (float*)d_out;

    static int inited = 0;
    const int smem1 = 2 * 2 * 128 * P1H * 2;      // 40,960
    const int smem2 = SM2_BYTES;                  // 93,888
    if (!inited) {
        cudaFuncSetAttribute(gemm_xg, cudaFuncAttributeMaxDynamicSharedMemorySize, smem1);
        cudaFuncSetAttribute(lstm_kernel, cudaFuncAttributeMaxDynamicSharedMemorySize, smem2);
        inited = 1;
    }

    prep_kernel<<<4096, 256>>>(x, W, U, bih, bhh);
    dim3 g1(32, 128);
    gemm_xg<<<g1, 256, smem1>>>();
    lstm_kernel<<<128, 256, smem2>>>(out);
}

// round 11
// speedup vs baseline: 1.6398x; 1.2096x over previous
#include <cuda_runtime.h>
#include <cuda_fp16.h>

// ---------------------------------------------------------------------------
// LSTM_6786048328562 : T=512, B=32, I=H=1024  (fp32 in/out, fp16 tensor math
//   with fp32 accumulate)
//   out = [ output(512*32*1024) | h_n(32*1024) | c_n(32*1024) ]
//
// Row reorder:  j'' = 32*blk + gate*8 + u   (hidden n = 8*blk + u, blk=0..127)
//
// prep    : reorder+fp16-round W,U; fp16 x; bias; zero h; bar=0
// gemm_xg : xg = xh @ Wh''^T + bias (m16n8k16 f16 mma, 128x128x32, 4-stage)
// lstm    : persistent 128 CTAs. Warp (nh,kh) split: nh = batch half (16),
//           kh = K quarter (256). A-fragments in regs (128). Single-phase
//           reduce (4 partials), gate math (c in regs), coalesced stores,
//           ONE release/acquire global barrier per step.
// ---------------------------------------------------------------------------

#define T_STEPS 512
#define BATCH   32
#define HID     1024
#define GATES   4096

__device__ float  d_xg[67108864];            // [16384][4096] fp32
__device__ __half d_xh[16777216];            // fp16 x
__device__ __half d_Wh[GATES * HID];
__device__ __half d_Uh[GATES * HID];
__device__ float  d_biasp[GATES];
__device__ __half d_hbuf[2 * BATCH * HID];   // double-buffered h (fp16)
__device__ unsigned g_bar;

__device__ __forceinline__ void mma_f16(float* c, const unsigned* a, const unsigned* b) {
    asm volatile(
        "mma.sync.aligned.m16n8k16.row.col.f32.f16.f16.f32 "
        "{%0,%1,%2,%3}, {%4,%5,%6,%7}, {%8,%9}, {%0,%1,%2,%3};\n"
        : "+f"(c[0]), "+f"(c[1]), "+f"(c[2]), "+f"(c[3])
        : "r"(a[0]), "r"(a[1]), "r"(a[2]), "r"(a[3]), "r"(b[0]), "r"(b[1]));
}

__device__ __forceinline__ float sigm(float x) { return 1.0f / (1.0f + expf(-x)); }

#define CP_ASYNC_CG(dst, src) \
    asm volatile("cp.async.cg.shared.global [%0], [%1], 16;\n" :: "r"(dst), "l"(src))
#define CP_COMMIT() asm volatile("cp.async.commit_group;\n")
#define CP_WAIT(n)  asm volatile("cp.async.wait_group %0;\n" :: "n"(n))

// ---------------------------------------------------------------------------
__global__ void prep_kernel(const float* __restrict__ x,
                            const float* __restrict__ W, const float* __restrict__ U,
                            const float* __restrict__ bih, const float* __restrict__ bhh) {
    int tid = blockIdx.x * blockDim.x + threadIdx.x;
    int stride = gridDim.x * blockDim.x;
    if (tid == 0) g_bar = 0u;

    for (int idx = tid; idx < GATES * HID; idx += stride) {
        int jp = idx >> 10, k = idx & 1023;
        int blk = jp >> 5, r = jp & 31;
        int gate = r >> 3, u = r & 7;
        int j = gate * HID + (blk * 8 + u);
        d_Wh[idx] = __float2half_rn(W[j * HID + k]);
        d_Uh[idx] = __float2half_rn(U[j * HID + k]);
    }
    for (int idx = tid; idx < 16777216; idx += stride)
        d_xh[idx] = __float2half_rn(x[idx]);
    for (int idx = tid; idx < GATES; idx += stride) {
        int blk = idx >> 5, r = idx & 31;
        int gate = r >> 3, u = r & 7;
        int j = gate * HID + (blk * 8 + u);
        d_biasp[idx] = bih[j] + bhh[j];
    }
    for (int idx = tid; idx < 2 * BATCH * HID; idx += stride)
        d_hbuf[idx] = __float2half_rn(0.0f);
}

// ---------------------------------------------------------------------------
// Phase 1: xg = xh @ Wh^T + bias   (M=16384, N=4096, K=1024), fp16 mma.
// 128x128 CTA tile, BK=32, 8 warps (2m x 4n), 4-stage cp.async pipeline.
// ---------------------------------------------------------------------------
#define P1H 40   // half stride per 32-k row
#define P1_STAGE (128 * P1H)

__global__ __launch_bounds__(256, 2) void gemm_xg() {
    extern __shared__ __half sm1[];
    __half* As = sm1;                    // [4][128*P1H]
    __half* Bs = sm1 + 4 * P1_STAGE;     // [4][128*P1H]

    const int n0 = blockIdx.x * 128;
    const int m0 = blockIdx.y * 128;
    const int tid = threadIdx.x;
    const int warp = tid >> 5, lane = tid & 31;
    const int wm = warp >> 2, wn = warp & 3;
    const int gid = lane >> 2, tg = lane & 3;

    float acc[4][4][4];
#pragma unroll
    for (int i = 0; i < 4; i++)
#pragma unroll
        for (int j = 0; j < 4; j++)
#pragma unroll
            for (int k = 0; k < 4; k++) acc[i][j][k] = 0.0f;

    const __half* Ag = d_xh + (size_t)m0 * HID;
    const __half* Bg = d_Wh + (size_t)n0 * HID;

    auto load_stage = [&](int kt, int st) {
        __half* Ad = As + st * P1_STAGE;
        __half* Bd = Bs + st * P1_STAGE;
        const int k0 = kt * 32;
#pragma unroll
        for (int l = 0; l < 2; l++) {
            int i = tid + l * 256;
            int row = i >> 2, seg = i & 3;
            unsigned da = (unsigned)__cvta_generic_to_shared(Ad + row * P1H + seg * 8);
            CP_ASYNC_CG(da, Ag + (size_t)row * HID + k0 + seg * 8);
            unsigned db = (unsigned)__cvta_generic_to_shared(Bd + row * P1H + seg * 8);
            CP_ASYNC_CG(db, Bg + (size_t)row * HID + k0 + seg * 8);
        }
        CP_COMMIT();
    };

    load_stage(0, 0);
    load_stage(1, 1);
    load_stage(2, 2);
    for (int kt = 0; kt < 32; kt++) {
        if (kt < 30)       { CP_WAIT(2); }
        else if (kt == 30) { CP_WAIT(1); }
        else               { CP_WAIT(0); }
        __syncthreads();
        if (kt + 3 < 32) load_stage(kt + 3, (kt + 3) & 3);

        const __half* Ac = As + (kt & 3) * P1_STAGE;
        const __half* Bc = Bs + (kt & 3) * P1_STAGE;
#pragma unroll
        for (int ks = 0; ks < 2; ks++) {
            const int kb = ks * 16;
            unsigned a[4][4], b[4][2];
#pragma unroll
            for (int mf = 0; mf < 4; mf++) {
                int row = wm * 64 + mf * 16 + gid;
                a[mf][0] = *(const unsigned*)&Ac[row * P1H + kb + 2 * tg];
                a[mf][1] = *(const unsigned*)&Ac[(row + 8) * P1H + kb + 2 * tg];
                a[mf][2] = *(const unsigned*)&Ac[row * P1H + kb + 8 + 2 * tg];
                a[mf][3] = *(const unsigned*)&Ac[(row + 8) * P1H + kb + 8 + 2 * tg];
            }
#pragma unroll
            for (int nf = 0; nf < 4; nf++) {
                int col = wn * 32 + nf * 8 + gid;
                b[nf][0] = *(const unsigned*)&Bc[col * P1H + kb + 2 * tg];
                b[nf][1] = *(const unsigned*)&Bc[col * P1H + kb + 8 + 2 * tg];
            }
#pragma unroll
            for (int mf = 0; mf < 4; mf++)
#pragma unroll
                for (int nf = 0; nf < 4; nf++) mma_f16(acc[mf][nf], a[mf], b[nf]);
        }
    }
    __syncthreads();

#pragma unroll
    for (int mf = 0; mf < 4; mf++)
#pragma unroll
        for (int nf = 0; nf < 4; nf++) {
            int row = m0 + wm * 64 + mf * 16 + gid;
            int col = n0 + wn * 32 + nf * 8 + 2 * tg;
            float b0 = d_biasp[col], b1 = d_biasp[col + 1];
            d_xg[(size_t)row * GATES + col]           = acc[mf][nf][0] + b0;
            d_xg[(size_t)row * GATES + col + 1]       = acc[mf][nf][1] + b1;
            d_xg[(size_t)(row + 8) * GATES + col]     = acc[mf][nf][2] + b0;
            d_xg[(size_t)(row + 8) * GATES + col + 1] = acc[mf][nf][3] + b1;
        }
}

// ---------------------------------------------------------------------------
// Phase 2: persistent recurrence, fp16 MMA. 128 CTAs, 32 gate-rows, full K.
// Warp w: nh = w>>2 (batch half), kh = w&3 (K quarter; 128 per chunk).
// smem: hs 2x[32][520] half | rb 2x(16 skew + 4x[32][18]) f32 |
//       xs 2x[32][36] f32 | hstg [32][9] f32
// ---------------------------------------------------------------------------
#define SH2 520
#define HS_CH (32 * SH2)
#define HS_BYTES (2 * HS_CH * 2)             // 66,560
#define RB_OFF HS_BYTES
#define RB_ROW 18
#define RB_BUF (32 * RB_ROW)                 // 576
#define RB_NH (16 + 4 * RB_BUF)              // 2320 (16-float bank skew)
#define XS_OFF (RB_OFF + 2 * RB_NH * 4)      // 85,120
#define HSTG_OFF (XS_OFF + 2 * 32 * 36 * 4)  // 94,336
#define SM2_BYTES (HSTG_OFF + 32 * 9 * 4 + 64) // 95,552

__global__ __launch_bounds__(256, 1) void lstm_kernel(float* __restrict__ out) {
    extern __shared__ char smc[];
    __half* hs   = (__half*)smc;
    float*  rb   = (float*)(smc + RB_OFF);
    float*  xs   = (float*)(smc + XS_OFF);
    float*  hstg = (float*)(smc + HSTG_OFF);

    const int cta = blockIdx.x;
    const int tid = threadIdx.x;
    const int warp = tid >> 5, lane = tid & 31;
    const int gid = lane >> 2, tg = lane & 3;
    const int nh = warp >> 2, kh = warp & 3;

    const unsigned long long barp =
        (unsigned long long)__cvta_generic_to_global(&g_bar);

    // ---- stage U'' fragments into registers (one-time, via hs scratch) ----
    unsigned aF[2][8][2][4];
    {
        const __half* Ug = d_Uh + (size_t)(32 * cta) * HID;
        for (int ch = 0; ch < 2; ch++) {
            for (int i = tid; i < 32 * 64; i += 256) {
                int row = i >> 6, seg = i & 63;
                *(float4*)(hs + row * SH2 + seg * 8) =
                    *(const float4*)(Ug + row * HID + ch * 512 + seg * 8);
            }
            __syncthreads();
#pragma unroll
            for (int ks = 0; ks < 8; ks++) {
                const int kc = kh * 128 + ks * 16 + 2 * tg;
#pragma unroll
                for (int mt = 0; mt < 2; mt++) {
                    int row = mt * 16 + gid;
                    aF[ch][ks][mt][0] = *(const unsigned*)&hs[row * SH2 + kc];
                    aF[ch][ks][mt][1] = *(const unsigned*)&hs[(row + 8) * SH2 + kc];
                    aF[ch][ks][mt][2] = *(const unsigned*)&hs[row * SH2 + kc + 8];
                    aF[ch][ks][mt][3] = *(const unsigned*)&hs[(row + 8) * SH2 + kc + 8];
                }
            }
            __syncthreads();
        }
    }

    // prefetch xg for t=0 into xs[0]
    {
        int row = tid >> 3, q = tid & 7;
        unsigned d = (unsigned)__cvta_generic_to_shared(xs + row * 36 + q * 4);
        CP_ASYNC_CG(d, d_xg + (size_t)row * GATES + 32 * cta + q * 4);
        CP_COMMIT();
    }

    const int tu = tid >> 5, tb = tid & 31;   // gate-math owner (u=tu, b=tb)
    float c_reg = 0.0f;

    // coalesced-store mapping: warp w -> b = 4w + lane>>3, u = lane&7
    const int wb = 4 * warp + (lane >> 3);
    const int wu = lane & 7;
    const int wn_idx = 8 * cta + wu;

    // reduce dump/gather bases
    float* rbd = rb + nh * RB_NH + kh * RB_BUF;
    const int nh_g = tb >> 4, bl = tb & 15;
    const float* rbg = rb + nh_g * RB_NH;

    for (int t = 0; t < T_STEPS; t++) {
        const __half* hb = d_hbuf + (t & 1) * (BATCH * HID);

        // issue xg(t+1) prefetch + both h chunks
        if (t + 1 < T_STEPS) {
            int row = tid >> 3, q = tid & 7;
            unsigned d = (unsigned)__cvta_generic_to_shared(
                xs + ((t + 1) & 1) * (32 * 36) + row * 36 + q * 4);
            CP_ASYNC_CG(d, d_xg + (size_t)((t + 1) * BATCH + row) * GATES
                            + 32 * cta + q * 4);
            CP_COMMIT();
        }
#pragma unroll
        for (int ch = 0; ch < 2; ch++) {
#pragma unroll
            for (int l = 0; l < 8; l++) {
                int i = tid + l * 256;
                int row = i >> 6, seg = i & 63;
                unsigned d = (unsigned)__cvta_generic_to_shared(
                    hs + ch * HS_CH + row * SH2 + seg * 8);
                CP_ASYNC_CG(d, hb + row * HID + ch * 512 + seg * 8);
            }
            CP_COMMIT();
        }

        float acc[2][2][4];
#pragma unroll
        for (int i = 0; i < 2; i++)
#pragma unroll
            for (int j = 0; j < 2; j++)
#pragma unroll
                for (int k = 0; k < 4; k++) acc[i][j][k] = 0.0f;

        auto mma_chunk = [&](int ch) {
            const __half* hc = hs + ch * HS_CH;
#pragma unroll
            for (int ks = 0; ks < 8; ks++) {
                const int kcl = kh * 128 + ks * 16 + 2 * tg;
#pragma unroll
                for (int nf = 0; nf < 2; nf++) {
                    unsigned b[2];
                    int brow = (nh * 16 + nf * 8 + gid) * SH2;
                    b[0] = *(const unsigned*)&hc[brow + kcl];
                    b[1] = *(const unsigned*)&hc[brow + kcl + 8];
#pragma unroll
                    for (int mt = 0; mt < 2; mt++)
                        mma_f16(acc[mt][nf], aF[ch][ks][mt], b);
                }
            }
        };

        CP_WAIT(1); __syncthreads(); mma_chunk(0);
        CP_WAIT(0); __syncthreads(); mma_chunk(1);

        // single-phase reduce: every warp dumps its (nh,kh) partial
#pragma unroll
        for (int mt = 0; mt < 2; mt++)
#pragma unroll
            for (int nf = 0; nf < 2; nf++) {
                int row = mt * 16 + gid;
                int col = nf * 8 + 2 * tg;
                rbd[row * RB_ROW + col]           = acc[mt][nf][0];
                rbd[row * RB_ROW + col + 1]       = acc[mt][nf][1];
                rbd[(row + 8) * RB_ROW + col]     = acc[mt][nf][2];
                rbd[(row + 8) * RB_ROW + col + 1] = acc[mt][nf][3];
            }
        __syncthreads();

        // gate math (thread owns u=tu, b=tb); 4 partials (kh) + xg
        float c_save = 0.0f;
        {
            const float* xgr = xs + (t & 1) * (32 * 36) + tb * 36;
            float v[4];
#pragma unroll
            for (int gate = 0; gate < 4; gate++) {
                int r = gate * 8 + tu;
                float s = xgr[r];
#pragma unroll
                for (int p = 0; p < 4; p++)
                    s += rbg[p * RB_BUF + r * RB_ROW + bl];
                v[gate] = s;
            }
            float it = sigm(v[0]);
            float ft = sigm(v[1]);
            float ch = tanhf(v[2]);
            float ot = sigm(v[3]);
            c_reg = ft * c_reg + it * ch;
            c_save = c_reg;
            float h = ot * tanhf(c_reg);
            hstg[tb * 9 + tu] = h;
        }
        __syncthreads();

        // coalesced fp16 h write to d_hbuf
        float hval = hstg[wb * 9 + wu];
        if (t + 1 < T_STEPS)
            d_hbuf[((t + 1) & 1) * (BATCH * HID) + wb * HID + wn_idx]
                = __float2half_rn(hval);

        __syncthreads();                    // order h stores before release
        if (tid == 0)
            asm volatile("red.release.gpu.global.add.u32 [%0], %1;"
                         :: "l"(barp), "r"(1u) : "memory");

        // out stores overlap the barrier spin
        out[(size_t)t * (BATCH * HID) + wb * HID + wn_idx] = hval;
        if (t == T_STEPS - 1) {
            out[16777216 + wb * HID + wn_idx] = hval;         // h_n
            __syncthreads();
            hstg[tb * 9 + tu] = c_save;
            __syncthreads();
            out[16777216 + 32768 + wb * HID + wn_idx] = hstg[wb * 9 + wu];
        }

        if (tid == 0) {
            const unsigned target = 128u * (unsigned)(t + 1);
            unsigned v;
            do {
                asm volatile("ld.acquire.gpu.global.u32 %0, [%1];"
                             : "=r"(v) : "l"(barp) : "memory");
            } while (v < target);
        }
        __syncthreads();
    }
}

// ---------------------------------------------------------------------------
extern "C" void kernel_launch(void* const* d_in, const int* in_sizes, int n_in,
                              void* d_out, int out_size) {
    (void)in_sizes; (void)n_in; (void)out_size;
    const float* x   = (const float*)d_in[0];
    const float* W   = (const float*)d_in[1];
    const float* U   = (const float*)d_in[2];
    const float* bih = (const float*)d_in[3];
    const float* bhh = (const float*)d_in[4];
    float* out = (float*)d_out;

    static int inited = 0;
    const int smem1 = 4 * 2 * P1_STAGE * 2;       // 81,920
    const int smem2 = SM2_BYTES;                  // 95,552
    if (!inited) {
        cudaFuncSetAttribute(gemm_xg, cudaFuncAttributeMaxDynamicSharedMemorySize, smem1);
        cudaFuncSetAttribute(lstm_kernel, cudaFuncAttributeMaxDynamicSharedMemorySize, smem2);
        inited = 1;
    }

    prep_kernel<<<4096, 256>>>(x, W, U, bih, bhh);
    dim3 g1(32, 128);
    gemm_xg<<<g1, 256, smem1>>>();
    lstm_kernel<<<128, 256, smem2>>>(out);
}

// round 12
// speedup vs baseline: 1.6575x; 1.0107x over previous
#include <cuda_runtime.h>
#include <cuda_fp16.h>

// ---------------------------------------------------------------------------
// LSTM_6786048328562 : T=512, B=32, I=H=1024  (fp32 in/out, fp16 tensor math
//   with fp32 accumulate)
//   out = [ output(512*32*1024) | h_n(32*1024) | c_n(32*1024) ]
//
// Row reorder:  j'' = 32*blk + gate*8 + u   (hidden n = 8*blk + u, blk=0..127)
//
// prep    : reorder+fp16-round W,U; fp16 x; bias; zero h; bar=0
// gemm_xg : xg = xh @ Wh''^T + bias (m16n8k16 f16 mma, 128x128x32, 4-stage)
// lstm    : persistent 128 CTAs. Warp (nh,kh) loads its OWN disjoint h slice
//           (16 b x 256 k) via cp.async + per-warp wait (no CTA syncs in the
//           load/mma path). A-fragments in regs (128). Single-phase reduce,
//           gate math owned by the coalescing thread (direct stores, no
//           transpose), fast exp-based activations, ONE release/acquire
//           global barrier per step. 3 CTA syncs/step total.
// ---------------------------------------------------------------------------

#define T_STEPS 512
#define BATCH   32
#define HID     1024
#define GATES   4096

__device__ float  d_xg[67108864];            // [16384][4096] fp32
__device__ __half d_xh[16777216];            // fp16 x
__device__ __half d_Wh[GATES * HID];
__device__ __half d_Uh[GATES * HID];
__device__ float  d_biasp[GATES];
__device__ __half d_hbuf[2 * BATCH * HID];   // double-buffered h (fp16)
__device__ unsigned g_bar;

__device__ __forceinline__ void mma_f16(float* c, const unsigned* a, const unsigned* b) {
    asm volatile(
        "mma.sync.aligned.m16n8k16.row.col.f32.f16.f16.f32 "
        "{%0,%1,%2,%3}, {%4,%5,%6,%7}, {%8,%9}, {%0,%1,%2,%3};\n"
        : "+f"(c[0]), "+f"(c[1]), "+f"(c[2]), "+f"(c[3])
        : "r"(a[0]), "r"(a[1]), "r"(a[2]), "r"(a[3]), "r"(b[0]), "r"(b[1]));
}

// fast activations: __expf (~2 ulp) + fast divide; clamp tanh arg (overflow)
__device__ __forceinline__ float sigm_f(float x) {
    float e = __expf(-x);
    return __fdividef(1.0f, 1.0f + e);
}
__device__ __forceinline__ float tanh_f(float x) {
    float xc = fminf(fmaxf(x, -10.0f), 10.0f);
    float e = __expf(2.0f * xc);
    return __fdividef(e - 1.0f, e + 1.0f);
}

#define CP_ASYNC_CG(dst, src) \
    asm volatile("cp.async.cg.shared.global [%0], [%1], 16;\n" :: "r"(dst), "l"(src))
#define CP_COMMIT() asm volatile("cp.async.commit_group;\n")
#define CP_WAIT(n)  asm volatile("cp.async.wait_group %0;\n" :: "n"(n))

// ---------------------------------------------------------------------------
__global__ void prep_kernel(const float* __restrict__ x,
                            const float* __restrict__ W, const float* __restrict__ U,
                            const float* __restrict__ bih, const float* __restrict__ bhh) {
    int tid = blockIdx.x * blockDim.x + threadIdx.x;
    int stride = gridDim.x * blockDim.x;
    if (tid == 0) g_bar = 0u;

    for (int idx = tid; idx < GATES * HID; idx += stride) {
        int jp = idx >> 10, k = idx & 1023;
        int blk = jp >> 5, r = jp & 31;
        int gate = r >> 3, u = r & 7;
        int j = gate * HID + (blk * 8 + u);
        d_Wh[idx] = __float2half_rn(W[j * HID + k]);
        d_Uh[idx] = __float2half_rn(U[j * HID + k]);
    }
    for (int idx = tid; idx < 16777216; idx += stride)
        d_xh[idx] = __float2half_rn(x[idx]);
    for (int idx = tid; idx < GATES; idx += stride) {
        int blk = idx >> 5, r = idx & 31;
        int gate = r >> 3, u = r & 7;
        int j = gate * HID + (blk * 8 + u);
        d_biasp[idx] = bih[j] + bhh[j];
    }
    for (int idx = tid; idx < 2 * BATCH * HID; idx += stride)
        d_hbuf[idx] = __float2half_rn(0.0f);
}

// ---------------------------------------------------------------------------
// Phase 1: xg = xh @ Wh^T + bias   (M=16384, N=4096, K=1024), fp16 mma.
// 128x128 CTA tile, BK=32, 8 warps (2m x 4n), 4-stage cp.async pipeline.
// ---------------------------------------------------------------------------
#define P1H 40
#define P1_STAGE (128 * P1H)

__global__ __launch_bounds__(256, 2) void gemm_xg() {
    extern __shared__ __half sm1[];
    __half* As = sm1;
    __half* Bs = sm1 + 4 * P1_STAGE;

    const int n0 = blockIdx.x * 128;
    const int m0 = blockIdx.y * 128;
    const int tid = threadIdx.x;
    const int warp = tid >> 5, lane = tid & 31;
    const int wm = warp >> 2, wn = warp & 3;
    const int gid = lane >> 2, tg = lane & 3;

    float acc[4][4][4];
#pragma unroll
    for (int i = 0; i < 4; i++)
#pragma unroll
        for (int j = 0; j < 4; j++)
#pragma unroll
            for (int k = 0; k < 4; k++) acc[i][j][k] = 0.0f;

    const __half* Ag = d_xh + (size_t)m0 * HID;
    const __half* Bg = d_Wh + (size_t)n0 * HID;

    auto load_stage = [&](int kt, int st) {
        __half* Ad = As + st * P1_STAGE;
        __half* Bd = Bs + st * P1_STAGE;
        const int k0 = kt * 32;
#pragma unroll
        for (int l = 0; l < 2; l++) {
            int i = tid + l * 256;
            int row = i >> 2, seg = i & 3;
            unsigned da = (unsigned)__cvta_generic_to_shared(Ad + row * P1H + seg * 8);
            CP_ASYNC_CG(da, Ag + (size_t)row * HID + k0 + seg * 8);
            unsigned db = (unsigned)__cvta_generic_to_shared(Bd + row * P1H + seg * 8);
            CP_ASYNC_CG(db, Bg + (size_t)row * HID + k0 + seg * 8);
        }
        CP_COMMIT();
    };

    load_stage(0, 0);
    load_stage(1, 1);
    load_stage(2, 2);
    for (int kt = 0; kt < 32; kt++) {
        if (kt < 30)       { CP_WAIT(2); }
        else if (kt == 30) { CP_WAIT(1); }
        else               { CP_WAIT(0); }
        __syncthreads();
        if (kt + 3 < 32) load_stage(kt + 3, (kt + 3) & 3);

        const __half* Ac = As + (kt & 3) * P1_STAGE;
        const __half* Bc = Bs + (kt & 3) * P1_STAGE;
#pragma unroll
        for (int ks = 0; ks < 2; ks++) {
            const int kb = ks * 16;
            unsigned a[4][4], b[4][2];
#pragma unroll
            for (int mf = 0; mf < 4; mf++) {
                int row = wm * 64 + mf * 16 + gid;
                a[mf][0] = *(const unsigned*)&Ac[row * P1H + kb + 2 * tg];
                a[mf][1] = *(const unsigned*)&Ac[(row + 8) * P1H + kb + 2 * tg];
                a[mf][2] = *(const unsigned*)&Ac[row * P1H + kb + 8 + 2 * tg];
                a[mf][3] = *(const unsigned*)&Ac[(row + 8) * P1H + kb + 8 + 2 * tg];
            }
#pragma unroll
            for (int nf = 0; nf < 4; nf++) {
                int col = wn * 32 + nf * 8 + gid;
                b[nf][0] = *(const unsigned*)&Bc[col * P1H + kb + 2 * tg];
                b[nf][1] = *(const unsigned*)&Bc[col * P1H + kb + 8 + 2 * tg];
            }
#pragma unroll
            for (int mf = 0; mf < 4; mf++)
#pragma unroll
                for (int nf = 0; nf < 4; nf++) mma_f16(acc[mf][nf], a[mf], b[nf]);
        }
    }
    __syncthreads();

#pragma unroll
    for (int mf = 0; mf < 4; mf++)
#pragma unroll
        for (int nf = 0; nf < 4; nf++) {
            int row = m0 + wm * 64 + mf * 16 + gid;
            int col = n0 + wn * 32 + nf * 8 + 2 * tg;
            float b0 = d_biasp[col], b1 = d_biasp[col + 1];
            d_xg[(size_t)row * GATES + col]           = acc[mf][nf][0] + b0;
            d_xg[(size_t)row * GATES + col + 1]       = acc[mf][nf][1] + b1;
            d_xg[(size_t)(row + 8) * GATES + col]     = acc[mf][nf][2] + b0;
            d_xg[(size_t)(row + 8) * GATES + col + 1] = acc[mf][nf][3] + b1;
        }
}

// ---------------------------------------------------------------------------
// Phase 2: persistent recurrence, fp16 MMA. 128 CTAs, 32 gate-rows, full K.
// Warp w: nh = w>>2 (batch half), kh = w&3 (K quarter). Warp-private h slice:
// [2 halves][16 b][136 halves] (chunk c covers global k = c*512 + kh*128..+128).
// smem: hs 8 x 4352 half | rb 2 x (16 skew + 4 x [32][18]) f32 | xs 2x[32][36] f32
// ---------------------------------------------------------------------------
#define SLC_ROW 136                          // halves per slice row (128 + 8 pad)
#define SLC_HALF (16 * SLC_ROW)              // 2176 halves per chunk-half
#define SLC_WARP (2 * SLC_HALF)              // 4352 halves per warp
#define HS_BYTES (8 * SLC_WARP * 2)          // 69,632
#define RB_OFF HS_BYTES
#define RB_ROW 18
#define RB_BUF (32 * RB_ROW)                 // 576
#define RB_NH (16 + 4 * RB_BUF)              // 2320 (16-float bank skew)
#define XS_OFF (RB_OFF + 2 * RB_NH * 4)      // 88,192
#define SM2_BYTES (XS_OFF + 2 * 32 * 36 * 4 + 64) // 97,472

__global__ __launch_bounds__(256, 1) void lstm_kernel(float* __restrict__ out) {
    extern __shared__ char smc[];
    __half* hs = (__half*)smc;
    float*  rb = (float*)(smc + RB_OFF);
    float*  xs = (float*)(smc + XS_OFF);

    const int cta = blockIdx.x;
    const int tid = threadIdx.x;
    const int warp = tid >> 5, lane = tid & 31;
    const int gid = lane >> 2, tg = lane & 3;
    const int nh = warp >> 2, kh = warp & 3;

    const unsigned long long barp =
        (unsigned long long)__cvta_generic_to_global(&g_bar);

    // ---- stage U'' fragments into registers (one-time, via hs scratch) ----
    // aF[ch][ks][mt][4]: chunk ch (k in [512ch,+512)), warp k-range within
    // chunk = [128*kh, +128), ks = k16 step 0..7, mt = row-half. 128 regs.
    unsigned aF[2][8][2][4];
    {
        __half* scr = hs;                     // 32 x 520 staging
        const __half* Ug = d_Uh + (size_t)(32 * cta) * HID;
        for (int ch = 0; ch < 2; ch++) {
            for (int i = tid; i < 32 * 64; i += 256) {
                int row = i >> 6, seg = i & 63;
                *(float4*)(scr + row * 520 + seg * 8) =
                    *(const float4*)(Ug + row * HID + ch * 512 + seg * 8);
            }
            __syncthreads();
#pragma unroll
            for (int ks = 0; ks < 8; ks++) {
                const int kc = kh * 128 + ks * 16 + 2 * tg;
#pragma unroll
                for (int mt = 0; mt < 2; mt++) {
                    int row = mt * 16 + gid;
                    aF[ch][ks][mt][0] = *(const unsigned*)&scr[row * 520 + kc];
                    aF[ch][ks][mt][1] = *(const unsigned*)&scr[(row + 8) * 520 + kc];
                    aF[ch][ks][mt][2] = *(const unsigned*)&scr[row * 520 + kc + 8];
                    aF[ch][ks][mt][3] = *(const unsigned*)&scr[(row + 8) * 520 + kc + 8];
                }
            }
            __syncthreads();
        }
    }

    // prefetch xg for t=0 into xs[0]
    {
        int row = tid >> 3, q = tid & 7;
        unsigned d = (unsigned)__cvta_generic_to_shared(xs + row * 36 + q * 4);
        CP_ASYNC_CG(d, d_xg + (size_t)row * GATES + 32 * cta + q * 4);
        CP_COMMIT();
    }

    // gate-math ownership == coalescing layout: b = 4*warp + lane>>3, u = lane&7
    const int wb = 4 * warp + (lane >> 3);
    const int wu = lane & 7;
    const int wn_idx = 8 * cta + wu;
    float c_reg = 0.0f;

    // reduce dump/gather bases
    float* rbd = rb + nh * RB_NH + kh * RB_BUF;
    const int nh_g = wb >> 4, bl = wb & 15;
    const float* rbg = rb + nh_g * RB_NH;

    __half* wslice = hs + warp * SLC_WARP;

    for (int t = 0; t < T_STEPS; t++) {
        const __half* hb = d_hbuf + (t & 1) * (BATCH * HID);

        // issue warp-private h slice halves (2 groups) + xg prefetch (1 group)
#pragma unroll
        for (int ch = 0; ch < 2; ch++) {
            const __half* src = hb + (size_t)(nh * 16) * HID + ch * 512 + kh * 128;
            __half* dst = wslice + ch * SLC_HALF;
#pragma unroll
            for (int it = 0; it < 8; it++) {
                int idx = lane + it * 32;
                int row = idx >> 4, seg = idx & 15;
                unsigned d = (unsigned)__cvta_generic_to_shared(
                    dst + row * SLC_ROW + seg * 8);
                CP_ASYNC_CG(d, src + (size_t)row * HID + seg * 8);
            }
            CP_COMMIT();
        }
        {
            int tn = (t + 1 < T_STEPS) ? t + 1 : T_STEPS - 1;
            int row = tid >> 3, q = tid & 7;
            unsigned d = (unsigned)__cvta_generic_to_shared(
                xs + ((t + 1) & 1) * (32 * 36) + row * 36 + q * 4);
            CP_ASYNC_CG(d, d_xg + (size_t)(tn * BATCH + row) * GATES
                            + 32 * cta + q * 4);
            CP_COMMIT();
        }

        float acc[2][2][4];
#pragma unroll
        for (int i = 0; i < 2; i++)
#pragma unroll
            for (int j = 0; j < 2; j++)
#pragma unroll
                for (int k = 0; k < 4; k++) acc[i][j][k] = 0.0f;

        auto mma_chunk = [&](int ch) {
            const __half* hc = wslice + ch * SLC_HALF;
#pragma unroll
            for (int ks = 0; ks < 8; ks++) {
                const int kcl = ks * 16 + 2 * tg;
#pragma unroll
                for (int nf = 0; nf < 2; nf++) {
                    unsigned b[2];
                    int brow = (nf * 8 + gid) * SLC_ROW;
                    b[0] = *(const unsigned*)&hc[brow + kcl];
                    b[1] = *(const unsigned*)&hc[brow + kcl + 8];
#pragma unroll
                    for (int mt = 0; mt < 2; mt++)
                        mma_f16(acc[mt][nf], aF[ch][ks][mt], b);
                }
            }
        };

        // per-warp waits only — no CTA syncs in the load/mma path
        CP_WAIT(2); __syncwarp(); mma_chunk(0);
        CP_WAIT(1); __syncwarp(); mma_chunk(1);

        // single-phase reduce: every warp dumps its (nh,kh) partial
#pragma unroll
        for (int mt = 0; mt < 2; mt++)
#pragma unroll
            for (int nf = 0; nf < 2; nf++) {
                int row = mt * 16 + gid;
                int col = nf * 8 + 2 * tg;
                rbd[row * RB_ROW + col]           = acc[mt][nf][0];
                rbd[row * RB_ROW + col + 1]       = acc[mt][nf][1];
                rbd[(row + 8) * RB_ROW + col]     = acc[mt][nf][2];
                rbd[(row + 8) * RB_ROW + col + 1] = acc[mt][nf][3];
            }
        __syncthreads();   // S_reduce (also publishes this step's xs tile)

        // gate math — owner (wb, wu) stores everything directly (coalesced)
        float hval, c_save;
        {
            const float* xgr = xs + (t & 1) * (32 * 36) + wb * 36;
            float v[4];
#pragma unroll
            for (int gate = 0; gate < 4; gate++) {
                int r = gate * 8 + wu;
                float s = xgr[r];
#pragma unroll
                for (int p = 0; p < 4; p++)
                    s += rbg[p * RB_BUF + r * RB_ROW + bl];
                v[gate] = s;
            }
            float it = sigm_f(v[0]);
            float ft = sigm_f(v[1]);
            float ch = tanh_f(v[2]);
            float ot = sigm_f(v[3]);
            c_reg = ft * c_reg + it * ch;
            c_save = c_reg;
            hval = ot * tanh_f(c_reg);
        }

        if (t + 1 < T_STEPS)
            d_hbuf[((t + 1) & 1) * (BATCH * HID) + wb * HID + wn_idx]
                = __float2half_rn(hval);

        __syncthreads();   // S_prerelease: order h stores before release
        if (tid == 0)
            asm volatile("red.release.gpu.global.add.u32 [%0], %1;"
                         :: "l"(barp), "r"(1u) : "memory");

        // out stores overlap the barrier spin
        out[(size_t)t * (BATCH * HID) + wb * HID + wn_idx] = hval;
        if (t == T_STEPS - 1) {
            out[16777216 + wb * HID + wn_idx] = hval;          // h_n
            out[16777216 + 32768 + wb * HID + wn_idx] = c_save; // c_n
        }

        if (tid == 0) {
            const unsigned target = 128u * (unsigned)(t + 1);
            unsigned v;
            do {
                asm volatile("ld.acquire.gpu.global.u32 %0, [%1];"
                             : "=r"(v) : "l"(barp) : "memory");
            } while (v < target);
        }
        __syncthreads();   // S_spin
    }
}

// ---------------------------------------------------------------------------
extern "C" void kernel_launch(void* const* d_in, const int* in_sizes, int n_in,
                              void* d_out, int out_size) {
    (void)in_sizes; (void)n_in; (void)out_size;
    const float* x   = (const float*)d_in[0];
    const float* W   = (const float*)d_in[1];
    const float* U   = (const float*)d_in[2];
    const float* bih = (const float*)d_in[3];
    const float* bhh = (const float*)d_in[4];
    float* out = (float*)d_out;

    static int inited = 0;
    const int smem1 = 4 * 2 * P1_STAGE * 2;       // 81,920
    const int smem2 = SM2_BYTES;                  // 97,472
    if (!inited) {
        cudaFuncSetAttribute(gemm_xg, cudaFuncAttributeMaxDynamicSharedMemorySize, smem1);
        cudaFuncSetAttribute(lstm_kernel, cudaFuncAttributeMaxDynamicSharedMemorySize, smem2);
        inited = 1;
    }

    prep_kernel<<<4096, 256>>>(x, W, U, bih, bhh);
    dim3 g1(32, 128);
    gemm_xg<<<g1, 256, smem1>>>();
    lstm_kernel<<<128, 256, smem2>>>(out);
}